// round 15
// baseline (speedup 1.0000x reference)
#include <cuda_runtime.h>
#include <cstdint>

typedef unsigned long long ull;
#define NB 32768
#define NL 128

__device__ float  g_eps[NL * NB];       // eps[t][b]
__device__ float  g_muT[NL * NB];       // mu transposed: [t][b]
__device__ float  g_scr[3 * NL * NB];   // outputs transposed: [k][t][b]
__device__ float2 g_Xpack[127 * 40];    // W_ih1 col c: [c*40+j]=(Wi,Wf), [c*40+20+j]=(Wg,Wo)

__device__ __forceinline__ ull ffma2(ull a, ull b, ull c){
    ull d; asm("fma.rn.f32x2 %0, %1, %2, %3;" : "=l"(d) : "l"(a), "l"(b), "l"(c)); return d;
}
__device__ __forceinline__ ull addf2(ull a, ull b){
    ull d; asm("add.rn.f32x2 %0, %1, %2;" : "=l"(d) : "l"(a), "l"(b)); return d;
}
__device__ __forceinline__ ull dup2(float f){
    ull r; asm("mov.b64 %0, {%1, %1};" : "=l"(r) : "f"(f)); return r;
}
__device__ __forceinline__ float2 unpack2(ull v){
    float2 r; asm("mov.b64 {%0, %1}, %2;" : "=f"(r.x), "=f"(r.y) : "l"(v)); return r;
}
__device__ __forceinline__ float sigf(float x){ return __fdividef(1.0f, 1.0f + __expf(-x)); }
__device__ __forceinline__ float tanh_f(float x){
    float e = __expf(2.0f * x); return 1.0f - __fdividef(2.0f, 1.0f + e);
}

// JAX threefry2x32, key=(0,42), partitionable (validated R11)
#define TFR(r) { x0 += x1; x1 = __funnelshift_l(x1, x1, (r)); x1 ^= x0; }
__device__ __forceinline__ uint32_t tf_bits(uint32_t i){
    const uint32_t K0 = 0u, K1 = 42u, K2 = 0x1BD11BDAu ^ 42u;
    uint32_t x0 = K0, x1 = i + K1;
    TFR(13) TFR(15) TFR(26) TFR(6)  x0 += K1; x1 += K2 + 1u;
    TFR(17) TFR(29) TFR(16) TFR(24) x0 += K2; x1 += K0 + 2u;
    TFR(13) TFR(15) TFR(26) TFR(6)  x0 += K0; x1 += K1 + 3u;
    TFR(17) TFR(29) TFR(16) TFR(24) x0 += K1; x1 += K2 + 4u;
    TFR(13) TFR(15) TFR(26) TFR(6)  x0 += K2; x1 += K0 + 5u;
    return x0 ^ x1;
}
__device__ __forceinline__ float erfinv_f(float x){
    float w = -__logf(fmaf(x, -x, 1.0f)), p;
    if (w < 5.0f){
        w -= 2.5f;
        p = 2.81022636e-08f;
        p = fmaf(p, w, 3.43273939e-07f);  p = fmaf(p, w, -3.5233877e-06f);
        p = fmaf(p, w, -4.39150654e-06f); p = fmaf(p, w, 0.00021858087f);
        p = fmaf(p, w, -0.00125372503f);  p = fmaf(p, w, -0.00417768164f);
        p = fmaf(p, w, 0.246640727f);     p = fmaf(p, w, 1.50140941f);
    } else {
        w = __fsqrt_rn(w) - 3.0f;
        p = -0.000200214257f;
        p = fmaf(p, w, 0.000100950558f);  p = fmaf(p, w, 0.00134934322f);
        p = fmaf(p, w, -0.00367342844f);  p = fmaf(p, w, 0.00573950773f);
        p = fmaf(p, w, -0.0076224613f);   p = fmaf(p, w, 0.00943887047f);
        p = fmaf(p, w, 1.00167406f);      p = fmaf(p, w, 2.83297682f);
    }
    return p * x;
}
__global__ void eps_kernel(){
    uint32_t i = blockIdx.x * 256u + threadIdx.x;
    uint32_t bits = tf_bits(i);
    float u01 = __uint_as_float((bits >> 9) | 0x3f800000u) - 1.0f;
    const float mn = __uint_as_float(0xBF7FFFFFu);
    float u = fmaxf(mn, fmaf(u01, 2.0f, mn));
    g_eps[i] = __uint_as_float(0x3FB504F3u) * erfinv_f(u);
}

__global__ void xpack_kernel(const float* __restrict__ Wih1){
    int idx = blockIdx.x * 256 + threadIdx.x;
    if (idx >= 127*40) return;
    int c = idx / 40, q = idx - c*40;
    int j  = (q < 20) ? q : (q - 20);
    int r0 = (q < 20) ? j : (40 + j);
    int r1 = (q < 20) ? (20 + j) : (60 + j);
    g_Xpack[idx] = make_float2(Wih1[r0*127 + c], Wih1[r1*127 + c]);
}

__global__ void mu_transpose_kernel(const float* __restrict__ mu){
    __shared__ float tile[32][33];
    int t0 = blockIdx.x * 32, b0 = blockIdx.y * 32;
    int tx = threadIdx.x, ty = threadIdx.y;           // block (32,8)
#pragma unroll
    for (int r = 0; r < 32; r += 8)
        tile[ty + r][tx] = mu[(size_t)(b0 + ty + r) * NL + t0 + tx];
    __syncthreads();
#pragma unroll
    for (int r = 0; r < 32; r += 8)
        g_muT[(size_t)(t0 + ty + r) * NB + b0 + tx] = tile[tx][ty + r];
}

__global__ void out_transpose_kernel(float* __restrict__ out){
    __shared__ float tile[32][33];
    const float* src = g_scr + (size_t)blockIdx.z * NL * NB;
    float* dst = out + (size_t)blockIdx.z * NL * NB;
    int t0 = blockIdx.x * 32, b0 = blockIdx.y * 32;
    int tx = threadIdx.x, ty = threadIdx.y;
#pragma unroll
    for (int r = 0; r < 32; r += 8)
        tile[ty + r][tx] = src[(size_t)(t0 + ty + r) * NB + b0 + tx];
    __syncthreads();
#pragma unroll
    for (int r = 0; r < 32; r += 8)
        dst[(size_t)(b0 + ty + r) * NL + t0 + tx] = tile[tx][ty + r];
}

#define WH_STRIDE 42   // padded: quad addresses land on disjoint banks

struct __align__(16) Smem {
    float2 WH[20*WH_STRIDE]; // [j*42 + g*10 + q] = (Whh1[g*20+j][2q], ..[2q+1])
    float2 W2[160];          // [p*40+d] = (Wih2[2p][d], Wih2[2p+1][d]); d<20:h, d>=20:c
    float2 Wh2[8];
    float2 B2[4];
    float2 BIF[20];
    float2 BGO[20];
    float  hbuf[64*20];      // per-element h vectors (quad-shared)
};

struct ElemState {
    ull aIF[5], aGO[5];
    float c1[5];
    float h2x, h2y, c2x, c2y;
};

__device__ __forceinline__ void do_elem(
    ElemState& S, const Smem& sm, float* hrow, int j0, bool lead, int e, int t)
{
    const ull* uW2  = reinterpret_cast<const ull*>(sm.W2);
    const ull* uWh2 = reinterpret_cast<const ull*>(sm.Wh2);
    const ull* uB2  = reinterpret_cast<const ull*>(sm.B2);

    // load previous h (written by own quad last step)
    ull hE[10];
    const ull* hu = reinterpret_cast<const ull*>(hrow);
#pragma unroll
    for (int q = 0; q < 10; ++q) hE[q] = hu[q];
    __syncwarp();   // order: all quad lanes' loads before any lane's stores below

    ull G0=0, G1=0, G2=0, G3=0;
    float hnew[5];
#pragma unroll
    for (int k = 0; k < 5; ++k){
        const int j = j0 + k;
        const ulonglong2* wU = reinterpret_cast<const ulonglong2*>(sm.WH + j*WH_STRIDE);
        ull ai=0, af=0, ag=0, ao=0;
#pragma unroll
        for (int q = 0; q < 5; ++q){
            ulonglong2 wi = wU[q], wf = wU[5+q], wg = wU[10+q], wo = wU[15+q];
            ull h0 = hE[2*q], h1 = hE[2*q+1];
            ai = ffma2(h0, wi.x, ai); ai = ffma2(h1, wi.y, ai);
            af = ffma2(h0, wf.x, af); af = ffma2(h1, wf.y, af);
            ag = ffma2(h0, wg.x, ag); ag = ffma2(h1, wg.y, ag);
            ao = ffma2(h0, wo.x, ao); ao = ffma2(h1, wo.y, ao);
        }
        float2 vi = unpack2(ai), vf = unpack2(af), vg = unpack2(ag), vo = unpack2(ao);
        float2 xif = unpack2(S.aIF[k]), xgo = unpack2(S.aGO[k]);
        float ig = sigf(vi.x + vi.y + xif.x);
        float fg = sigf(vf.x + vf.y + xif.y);
        float gg = tanh_f(vg.x + vg.y + xgo.x);
        float og = sigf(vo.x + vo.y + xgo.y);
        float cn = fmaf(fg, S.c1[k], ig * gg);
        S.c1[k] = cn;
        float hj = og * tanh_f(cn);
        hnew[k] = hj;

        ull lh = dup2(fmaxf(hj, 0.01f * hj));
        G0 = ffma2(lh, uW2[j],       G0); G1 = ffma2(lh, uW2[40 + j],  G1);
        G2 = ffma2(lh, uW2[80 + j],  G2); G3 = ffma2(lh, uW2[120 + j], G3);
        ull lc = dup2(fmaxf(cn, 0.01f * cn));
        G0 = ffma2(lc, uW2[20 + j],  G0); G1 = ffma2(lc, uW2[60 + j],  G1);
        G2 = ffma2(lc, uW2[100 + j], G2); G3 = ffma2(lc, uW2[140 + j], G3);
    }
    // publish new h for next step
#pragma unroll
    for (int k = 0; k < 5; ++k) hrow[j0 + k] = hnew[k];

    // quad reduction of layer-2 gates
    G0 = addf2(G0, __shfl_xor_sync(0xffffffffu, G0, 1, 4));
    G0 = addf2(G0, __shfl_xor_sync(0xffffffffu, G0, 2, 4));
    G1 = addf2(G1, __shfl_xor_sync(0xffffffffu, G1, 1, 4));
    G1 = addf2(G1, __shfl_xor_sync(0xffffffffu, G1, 2, 4));
    G2 = addf2(G2, __shfl_xor_sync(0xffffffffu, G2, 1, 4));
    G2 = addf2(G2, __shfl_xor_sync(0xffffffffu, G2, 2, 4));
    G3 = addf2(G3, __shfl_xor_sync(0xffffffffu, G3, 1, 4));
    G3 = addf2(G3, __shfl_xor_sync(0xffffffffu, G3, 2, 4));
    G0 = addf2(G0, uB2[0]); G1 = addf2(G1, uB2[1]);
    G2 = addf2(G2, uB2[2]); G3 = addf2(G3, uB2[3]);
    {
        ull hx = dup2(S.h2x), hy = dup2(S.h2y);
        G0 = ffma2(hx, uWh2[0], G0); G0 = ffma2(hy, uWh2[1], G0);
        G1 = ffma2(hx, uWh2[2], G1); G1 = ffma2(hy, uWh2[3], G1);
        G2 = ffma2(hx, uWh2[4], G2); G2 = ffma2(hy, uWh2[5], G2);
        G3 = ffma2(hx, uWh2[6], G3); G3 = ffma2(hy, uWh2[7], G3);
    }
    float2 gi = unpack2(G0), gf = unpack2(G1), gg2 = unpack2(G2), go = unpack2(G3);
    float i0 = sigf(gi.x),    i1 = sigf(gi.y);
    float f0 = sigf(gf.x),    f1 = sigf(gf.y);
    float t0 = tanh_f(gg2.x), t1 = tanh_f(gg2.y);
    float o0 = sigf(go.x),    o1 = sigf(go.y);
    S.c2x = fmaf(f0, S.c2x, i0 * t0);
    S.c2y = fmaf(f1, S.c2y, i1 * t1);
    S.h2x = o0 * tanh_f(S.c2x);
    S.h2y = o1 * tanh_f(S.c2y);

    if (lead){
        size_t o = (size_t)t * NB + e;
        g_scr[o]               = S.h2x;
        g_scr[(size_t)NL*NB + o]   = S.h2y;
        g_scr[(size_t)2*NL*NB + o] = fmaf(g_eps[o], __expf(0.5f * S.h2y), S.h2x);
    }
}

__global__ void __launch_bounds__(128, 3) lstm_kernel(
    const float* __restrict__ log_var,
    const float* __restrict__ Whh1,
    const float* __restrict__ bih1, const float* __restrict__ bhh1,
    const float* __restrict__ Wih2, const float* __restrict__ Whh2,
    const float* __restrict__ bih2, const float* __restrict__ bhh2)
{
    __shared__ Smem sm;
    const int tid = threadIdx.x;

    for (int idx = tid; idx < 800; idx += 128){
        int j = idx / 40, r = idx - j*40;
        int gg = r / 10, q = r - gg*10;
        int row = gg*20 + j;
        sm.WH[j*WH_STRIDE + r] = make_float2(Whh1[row*20 + 2*q], Whh1[row*20 + 2*q + 1]);
    }
    for (int idx = tid; idx < 160; idx += 128){
        int p = idx / 40, d = idx - p*40;
        sm.W2[idx] = make_float2(Wih2[(2*p)*40 + d], Wih2[(2*p+1)*40 + d]);
    }
    if (tid < 8){
        int p = tid >> 1, e = tid & 1;
        sm.Wh2[tid] = make_float2(Whh2[(2*p)*2 + e], Whh2[(2*p+1)*2 + e]);
    }
    if (tid < 4)
        sm.B2[tid] = make_float2(bih2[2*tid] + bhh2[2*tid], bih2[2*tid+1] + bhh2[2*tid+1]);
    if (tid < 20){
        sm.BIF[tid] = make_float2(bih1[tid]    + bhh1[tid],    bih1[20+tid] + bhh1[20+tid]);
        sm.BGO[tid] = make_float2(bih1[40+tid] + bhh1[40+tid], bih1[60+tid] + bhh1[60+tid]);
    }
    __syncthreads();

    const int g    = tid & 3;
    const int j0   = g * 5;
    const int quad = (tid & 31) >> 2;
    const int wrp  = tid >> 5;
    const int eb   = blockIdx.x * 64 + wrp * 16;
    const int eA   = eb + quad;
    const int eB   = eb + 8 + quad;
    const bool lead = (g == 0);

    float* hrowA = sm.hbuf + (wrp*16 + quad) * 20;
    float* hrowB = sm.hbuf + (wrp*16 + 8 + quad) * 20;

    const ull* uBIF = reinterpret_cast<const ull*>(sm.BIF);
    const ull* uBGO = reinterpret_cast<const ull*>(sm.BGO);
    const ull* Xu   = reinterpret_cast<const ull*>(g_Xpack);

    ElemState SA, SB;
#pragma unroll
    for (int k = 0; k < 5; ++k){
        SA.aIF[k] = uBIF[j0+k]; SA.aGO[k] = uBGO[j0+k];
        SB.aIF[k] = SA.aIF[k];  SB.aGO[k] = SA.aGO[k];
        SA.c1[k] = 0.0f; SB.c1[k] = 0.0f;
        hrowA[j0+k] = 0.0f; hrowB[j0+k] = 0.0f;
    }
    SA.h2x=SA.h2y=SA.c2x=SA.c2y=0.f;
    SB.h2x=SB.h2y=SB.c2x=SB.c2y=0.f;
    __syncwarp();

    const float mu0A = __ldg(&g_muT[eA]),  mu0B = __ldg(&g_muT[eB]);
    const float firstA = fmaf(g_eps[eA], __expf(0.5f * __ldg(&log_var[(size_t)eA * NL])), mu0A);
    const float firstB = fmaf(g_eps[eB], __expf(0.5f * __ldg(&log_var[(size_t)eB * NL])), mu0B);
    const float dA = mu0A - firstA, dB = mu0B - firstB;
    if (lead){
        g_scr[eA] = 0.0f; g_scr[(size_t)NL*NB + eA] = 1.0f; g_scr[(size_t)2*NL*NB + eA] = firstA;
        g_scr[eB] = 0.0f; g_scr[(size_t)NL*NB + eB] = 1.0f; g_scr[(size_t)2*NL*NB + eB] = firstB;
    }

    {   // step-1 x-proj: col 0 * first_input
        ull fA = dup2(firstA), fB = dup2(firstB);
#pragma unroll
        for (int k = 0; k < 5; ++k){
            ull wi = __ldg(&Xu[j0 + k]), wg = __ldg(&Xu[20 + j0 + k]);
            SA.aIF[k] = ffma2(fA, wi, SA.aIF[k]); SA.aGO[k] = ffma2(fA, wg, SA.aGO[k]);
            SB.aIF[k] = ffma2(fB, wi, SB.aIF[k]); SB.aGO[k] = ffma2(fB, wg, SB.aGO[k]);
        }
    }

#pragma unroll 1
    for (int t = 1; t < NL; ++t){
        do_elem(SA, sm, hrowA, j0, lead, eA, t);
        do_elem(SB, sm, hrowB, j0, lead, eB, t);

        if (t < 127){   // rank-1 x-projection update (weights shared A/B)
            ull mA = dup2(__ldg(&g_muT[(size_t)t * NB + eA]));
            ull mB = dup2(__ldg(&g_muT[(size_t)t * NB + eB]));
            const ull* xc = Xu + t * 40;
#pragma unroll
            for (int k = 0; k < 5; ++k){
                ull wi = __ldg(&xc[j0 + k]), wg = __ldg(&xc[20 + j0 + k]);
                SA.aIF[k] = ffma2(mA, wi, SA.aIF[k]); SA.aGO[k] = ffma2(mA, wg, SA.aGO[k]);
                SB.aIF[k] = ffma2(mB, wi, SB.aIF[k]); SB.aGO[k] = ffma2(mB, wg, SB.aGO[k]);
            }
            if (t == 1){   // col 0 switches first_input -> mu[:,0] after step 1
                ull pA = dup2(dA), pB = dup2(dB);
#pragma unroll
                for (int k = 0; k < 5; ++k){
                    ull wi = __ldg(&Xu[j0 + k]), wg = __ldg(&Xu[20 + j0 + k]);
                    SA.aIF[k] = ffma2(pA, wi, SA.aIF[k]); SA.aGO[k] = ffma2(pA, wg, SA.aGO[k]);
                    SB.aIF[k] = ffma2(pB, wi, SB.aIF[k]); SB.aGO[k] = ffma2(pB, wg, SB.aGO[k]);
                }
            }
        }
    }
}

extern "C" void kernel_launch(void* const* d_in, const int* in_sizes, int n_in,
                              void* d_out, int out_size){
    (void)in_sizes; (void)n_in; (void)out_size;
    dim3 tb(32, 8);
    xpack_kernel<<<20, 256>>>((const float*)d_in[2]);
    mu_transpose_kernel<<<dim3(NL/32, NB/32), tb>>>((const float*)d_in[0]);
    eps_kernel<<<(NL * NB) / 256, 256>>>();
    lstm_kernel<<<NB / 64, 128>>>(
        (const float*)d_in[1],
        (const float*)d_in[3],
        (const float*)d_in[4], (const float*)d_in[5],
        (const float*)d_in[6], (const float*)d_in[7],
        (const float*)d_in[8], (const float*)d_in[9]);
    out_transpose_kernel<<<dim3(NL/32, NB/32, 3), tb>>>((float*)d_out);
}

// round 16
// speedup vs baseline: 1.3330x; 1.3330x over previous
#include <cuda_runtime.h>
#include <cstdint>

typedef unsigned long long ull;
#define NB 32768
#define NL 128

__device__ float  g_eps[NL * NB];       // eps[t][b]
__device__ float  g_muT[NL * NB];       // mu transposed: [t][b]
__device__ float  g_scr[3 * NL * NB];   // outputs transposed: [k][t][b]
__device__ float2 g_Xpack[127 * 40];    // W_ih1 col c: [c*40+j]=(Wi,Wf), [c*40+20+j]=(Wg,Wo)

__device__ __forceinline__ ull ffma2(ull a, ull b, ull c){
    ull d; asm("fma.rn.f32x2 %0, %1, %2, %3;" : "=l"(d) : "l"(a), "l"(b), "l"(c)); return d;
}
__device__ __forceinline__ ull addf2(ull a, ull b){
    ull d; asm("add.rn.f32x2 %0, %1, %2;" : "=l"(d) : "l"(a), "l"(b)); return d;
}
__device__ __forceinline__ ull dup2(float f){
    ull r; asm("mov.b64 %0, {%1, %1};" : "=l"(r) : "f"(f)); return r;
}
__device__ __forceinline__ float2 unpack2(ull v){
    float2 r; asm("mov.b64 {%0, %1}, %2;" : "=f"(r.x), "=f"(r.y) : "l"(v)); return r;
}
__device__ __forceinline__ float sigf(float x){ return __fdividef(1.0f, 1.0f + __expf(-x)); }
__device__ __forceinline__ float tanh_f(float x){
    float e = __expf(2.0f * x); return 1.0f - __fdividef(2.0f, 1.0f + e);
}

// JAX threefry2x32, key=(0,42), partitionable (validated R11)
#define TFR(r) { x0 += x1; x1 = __funnelshift_l(x1, x1, (r)); x1 ^= x0; }
__device__ __forceinline__ uint32_t tf_bits(uint32_t i){
    const uint32_t K0 = 0u, K1 = 42u, K2 = 0x1BD11BDAu ^ 42u;
    uint32_t x0 = K0, x1 = i + K1;
    TFR(13) TFR(15) TFR(26) TFR(6)  x0 += K1; x1 += K2 + 1u;
    TFR(17) TFR(29) TFR(16) TFR(24) x0 += K2; x1 += K0 + 2u;
    TFR(13) TFR(15) TFR(26) TFR(6)  x0 += K0; x1 += K1 + 3u;
    TFR(17) TFR(29) TFR(16) TFR(24) x0 += K1; x1 += K2 + 4u;
    TFR(13) TFR(15) TFR(26) TFR(6)  x0 += K2; x1 += K0 + 5u;
    return x0 ^ x1;
}
__device__ __forceinline__ float erfinv_f(float x){
    float w = -__logf(fmaf(x, -x, 1.0f)), p;
    if (w < 5.0f){
        w -= 2.5f;
        p = 2.81022636e-08f;
        p = fmaf(p, w, 3.43273939e-07f);  p = fmaf(p, w, -3.5233877e-06f);
        p = fmaf(p, w, -4.39150654e-06f); p = fmaf(p, w, 0.00021858087f);
        p = fmaf(p, w, -0.00125372503f);  p = fmaf(p, w, -0.00417768164f);
        p = fmaf(p, w, 0.246640727f);     p = fmaf(p, w, 1.50140941f);
    } else {
        w = __fsqrt_rn(w) - 3.0f;
        p = -0.000200214257f;
        p = fmaf(p, w, 0.000100950558f);  p = fmaf(p, w, 0.00134934322f);
        p = fmaf(p, w, -0.00367342844f);  p = fmaf(p, w, 0.00573950773f);
        p = fmaf(p, w, -0.0076224613f);   p = fmaf(p, w, 0.00943887047f);
        p = fmaf(p, w, 1.00167406f);      p = fmaf(p, w, 2.83297682f);
    }
    return p * x;
}
__global__ void eps_kernel(){
    uint32_t i = blockIdx.x * 256u + threadIdx.x;
    uint32_t bits = tf_bits(i);
    float u01 = __uint_as_float((bits >> 9) | 0x3f800000u) - 1.0f;
    const float mn = __uint_as_float(0xBF7FFFFFu);
    float u = fmaxf(mn, fmaf(u01, 2.0f, mn));
    g_eps[i] = __uint_as_float(0x3FB504F3u) * erfinv_f(u);
}

__global__ void xpack_kernel(const float* __restrict__ Wih1){
    int idx = blockIdx.x * 256 + threadIdx.x;
    if (idx >= 127*40) return;
    int c = idx / 40, q = idx - c*40;
    int j  = (q < 20) ? q : (q - 20);
    int r0 = (q < 20) ? j : (40 + j);
    int r1 = (q < 20) ? (20 + j) : (60 + j);
    g_Xpack[idx] = make_float2(Wih1[r0*127 + c], Wih1[r1*127 + c]);
}

__global__ void mu_transpose_kernel(const float* __restrict__ mu){
    __shared__ float tile[32][33];
    int t0 = blockIdx.x * 32, b0 = blockIdx.y * 32;
    int tx = threadIdx.x, ty = threadIdx.y;           // block (32,8)
#pragma unroll
    for (int r = 0; r < 32; r += 8)
        tile[ty + r][tx] = mu[(size_t)(b0 + ty + r) * NL + t0 + tx];
    __syncthreads();
#pragma unroll
    for (int r = 0; r < 32; r += 8)
        g_muT[(size_t)(t0 + ty + r) * NB + b0 + tx] = tile[tx][ty + r];
}

__global__ void out_transpose_kernel(float* __restrict__ out){
    __shared__ float tile[32][33];
    const float* src = g_scr + (size_t)blockIdx.z * NL * NB;
    float* dst = out + (size_t)blockIdx.z * NL * NB;
    int t0 = blockIdx.x * 32, b0 = blockIdx.y * 32;
    int tx = threadIdx.x, ty = threadIdx.y;
#pragma unroll
    for (int r = 0; r < 32; r += 8)
        tile[ty + r][tx] = src[(size_t)(t0 + ty + r) * NB + b0 + tx];
    __syncthreads();
#pragma unroll
    for (int r = 0; r < 32; r += 8)
        dst[(size_t)(b0 + ty + r) * NL + t0 + tx] = tile[tx][ty + r];
}

#define WH_STRIDE 42   // padded: quad addresses land on disjoint banks

struct __align__(16) Smem {
    float2 WH[20*WH_STRIDE]; // [j*42 + g*10 + q] = (Whh1[g*20+j][2q], ..[2q+1])
    float2 W2[160];          // [p*40+d] = (Wih2[2p][d], Wih2[2p+1][d]); d<20:h, d>=20:c
    float2 Wh2[8];
    float2 B2[4];
    float2 BIF[20];
    float2 BGO[20];
    float  hbuf[64*20];      // per-element h vectors (quad-shared)
};

__global__ void __launch_bounds__(128, 3) lstm_kernel(
    const float* __restrict__ log_var,
    const float* __restrict__ Whh1,
    const float* __restrict__ bih1, const float* __restrict__ bhh1,
    const float* __restrict__ Wih2, const float* __restrict__ Whh2,
    const float* __restrict__ bih2, const float* __restrict__ bhh2)
{
    __shared__ Smem sm;
    const int tid = threadIdx.x;

    for (int idx = tid; idx < 800; idx += 128){
        int j = idx / 40, r = idx - j*40;
        int gg = r / 10, q = r - gg*10;
        int row = gg*20 + j;
        sm.WH[j*WH_STRIDE + r] = make_float2(Whh1[row*20 + 2*q], Whh1[row*20 + 2*q + 1]);
    }
    for (int idx = tid; idx < 160; idx += 128){
        int p = idx / 40, d = idx - p*40;
        sm.W2[idx] = make_float2(Wih2[(2*p)*40 + d], Wih2[(2*p+1)*40 + d]);
    }
    if (tid < 8){
        int p = tid >> 1, e = tid & 1;
        sm.Wh2[tid] = make_float2(Whh2[(2*p)*2 + e], Whh2[(2*p+1)*2 + e]);
    }
    if (tid < 4)
        sm.B2[tid] = make_float2(bih2[2*tid] + bhh2[2*tid], bih2[2*tid+1] + bhh2[2*tid+1]);
    if (tid < 20){
        sm.BIF[tid] = make_float2(bih1[tid]    + bhh1[tid],    bih1[20+tid] + bhh1[20+tid]);
        sm.BGO[tid] = make_float2(bih1[40+tid] + bhh1[40+tid], bih1[60+tid] + bhh1[60+tid]);
    }
    __syncthreads();

    const int g    = tid & 3;
    const int j0   = g * 5;
    const int quad = (tid & 31) >> 2;
    const int wrp  = tid >> 5;
    const int eb   = blockIdx.x * 64 + wrp * 16;
    const int eA   = eb + quad;
    const int eB   = eb + 8 + quad;
    const bool lead = (g == 0);

    float* hrowA = sm.hbuf + (wrp*16 + quad) * 20;
    float* hrowB = sm.hbuf + (wrp*16 + 8 + quad) * 20;

    const ull* uBIF = reinterpret_cast<const ull*>(sm.BIF);
    const ull* uBGO = reinterpret_cast<const ull*>(sm.BGO);
    const ull* Xu   = reinterpret_cast<const ull*>(g_Xpack);
    const ull* uW2  = reinterpret_cast<const ull*>(sm.W2);
    const ull* uWh2 = reinterpret_cast<const ull*>(sm.Wh2);
    const ull* uB2  = reinterpret_cast<const ull*>(sm.B2);

    ull aIFA[5], aGOA[5], aIFB[5], aGOB[5];
    float c1A[5], c1B[5];
#pragma unroll
    for (int k = 0; k < 5; ++k){
        aIFA[k] = uBIF[j0+k]; aGOA[k] = uBGO[j0+k];
        aIFB[k] = aIFA[k];    aGOB[k] = aGOA[k];
        c1A[k] = 0.0f; c1B[k] = 0.0f;
        hrowA[j0+k] = 0.0f; hrowB[j0+k] = 0.0f;
    }
    float h2xA=0.f,h2yA=0.f,c2xA=0.f,c2yA=0.f;
    float h2xB=0.f,h2yB=0.f,c2xB=0.f,c2yB=0.f;
    __syncwarp();

    const float mu0A = __ldg(&g_muT[eA]),  mu0B = __ldg(&g_muT[eB]);
    const float firstA = fmaf(g_eps[eA], __expf(0.5f * __ldg(&log_var[(size_t)eA * NL])), mu0A);
    const float firstB = fmaf(g_eps[eB], __expf(0.5f * __ldg(&log_var[(size_t)eB * NL])), mu0B);
    const float dA = mu0A - firstA, dB = mu0B - firstB;
    if (lead){
        g_scr[eA] = 0.0f; g_scr[(size_t)NL*NB + eA] = 1.0f; g_scr[(size_t)2*NL*NB + eA] = firstA;
        g_scr[eB] = 0.0f; g_scr[(size_t)NL*NB + eB] = 1.0f; g_scr[(size_t)2*NL*NB + eB] = firstB;
    }

    {   // step-1 x-proj: col 0 * first_input
        ull fA = dup2(firstA), fB = dup2(firstB);
#pragma unroll
        for (int k = 0; k < 5; ++k){
            ull wi = __ldg(&Xu[j0 + k]), wg = __ldg(&Xu[20 + j0 + k]);
            aIFA[k] = ffma2(fA, wi, aIFA[k]); aGOA[k] = ffma2(fA, wg, aGOA[k]);
            aIFB[k] = ffma2(fB, wi, aIFB[k]); aGOB[k] = ffma2(fB, wg, aGOB[k]);
        }
    }

#pragma unroll 1
    for (int t = 1; t < NL; ++t){
        // ---- load previous h for both elements (quad-shared smem) ----
        ull hEA[10], hEB[10];
        {
            const ull* ha = reinterpret_cast<const ull*>(hrowA);
            const ull* hb = reinterpret_cast<const ull*>(hrowB);
#pragma unroll
            for (int q = 0; q < 10; ++q){ hEA[q] = ha[q]; hEB[q] = hb[q]; }
        }
        __syncwarp();   // all quad lanes' reads precede any lane's stores below

        ull GA0=0,GA1=0,GA2=0,GA3=0, GB0=0,GB1=0,GB2=0,GB3=0;

#pragma unroll
        for (int k = 0; k < 5; ++k){
            const int j = j0 + k;
            const ulonglong2* wU = reinterpret_cast<const ulonglong2*>(sm.WH + j*WH_STRIDE);
            ull aiA=0,afA=0,agA=0,aoA=0, aiB=0,afB=0,agB=0,aoB=0;
#pragma unroll
            for (int q = 0; q < 5; ++q){
                ulonglong2 wi = wU[q], wf = wU[5+q], wg = wU[10+q], wo = wU[15+q];
                ull a0 = hEA[2*q], a1 = hEA[2*q+1];
                ull b0 = hEB[2*q], b1 = hEB[2*q+1];
                aiA = ffma2(a0, wi.x, aiA); aiA = ffma2(a1, wi.y, aiA);
                afA = ffma2(a0, wf.x, afA); afA = ffma2(a1, wf.y, afA);
                agA = ffma2(a0, wg.x, agA); agA = ffma2(a1, wg.y, agA);
                aoA = ffma2(a0, wo.x, aoA); aoA = ffma2(a1, wo.y, aoA);
                aiB = ffma2(b0, wi.x, aiB); aiB = ffma2(b1, wi.y, aiB);
                afB = ffma2(b0, wf.x, afB); afB = ffma2(b1, wf.y, afB);
                agB = ffma2(b0, wg.x, agB); agB = ffma2(b1, wg.y, agB);
                aoB = ffma2(b0, wo.x, aoB); aoB = ffma2(b1, wo.y, aoB);
            }
            // shared layer-2 weight loads
            ull w2h0 = uW2[j],    w2h1 = uW2[40+j],  w2h2 = uW2[80+j],  w2h3 = uW2[120+j];
            ull w2c0 = uW2[20+j], w2c1 = uW2[60+j],  w2c2 = uW2[100+j], w2c3 = uW2[140+j];
            {   // element A cell
                float2 vi=unpack2(aiA), vf=unpack2(afA), vg=unpack2(agA), vo=unpack2(aoA);
                float2 xif=unpack2(aIFA[k]), xgo=unpack2(aGOA[k]);
                float ig = sigf(vi.x + vi.y + xif.x);
                float fg = sigf(vf.x + vf.y + xif.y);
                float gg = tanh_f(vg.x + vg.y + xgo.x);
                float og = sigf(vo.x + vo.y + xgo.y);
                float cn = fmaf(fg, c1A[k], ig * gg);
                c1A[k] = cn;
                float hj = og * tanh_f(cn);
                hrowA[j] = hj;
                ull lh = dup2(fmaxf(hj, 0.01f * hj));
                GA0 = ffma2(lh, w2h0, GA0); GA1 = ffma2(lh, w2h1, GA1);
                GA2 = ffma2(lh, w2h2, GA2); GA3 = ffma2(lh, w2h3, GA3);
                ull lc = dup2(fmaxf(cn, 0.01f * cn));
                GA0 = ffma2(lc, w2c0, GA0); GA1 = ffma2(lc, w2c1, GA1);
                GA2 = ffma2(lc, w2c2, GA2); GA3 = ffma2(lc, w2c3, GA3);
            }
            {   // element B cell
                float2 vi=unpack2(aiB), vf=unpack2(afB), vg=unpack2(agB), vo=unpack2(aoB);
                float2 xif=unpack2(aIFB[k]), xgo=unpack2(aGOB[k]);
                float ig = sigf(vi.x + vi.y + xif.x);
                float fg = sigf(vf.x + vf.y + xif.y);
                float gg = tanh_f(vg.x + vg.y + xgo.x);
                float og = sigf(vo.x + vo.y + xgo.y);
                float cn = fmaf(fg, c1B[k], ig * gg);
                c1B[k] = cn;
                float hj = og * tanh_f(cn);
                hrowB[j] = hj;
                ull lh = dup2(fmaxf(hj, 0.01f * hj));
                GB0 = ffma2(lh, w2h0, GB0); GB1 = ffma2(lh, w2h1, GB1);
                GB2 = ffma2(lh, w2h2, GB2); GB3 = ffma2(lh, w2h3, GB3);
                ull lc = dup2(fmaxf(cn, 0.01f * cn));
                GB0 = ffma2(lc, w2c0, GB0); GB1 = ffma2(lc, w2c1, GB1);
                GB2 = ffma2(lc, w2c2, GB2); GB3 = ffma2(lc, w2c3, GB3);
            }
        }
        __syncwarp();   // stores complete before next step's loads

        // ---- quad reductions ----
        GA0 = addf2(GA0, __shfl_xor_sync(0xffffffffu, GA0, 1, 4));
        GA0 = addf2(GA0, __shfl_xor_sync(0xffffffffu, GA0, 2, 4));
        GA1 = addf2(GA1, __shfl_xor_sync(0xffffffffu, GA1, 1, 4));
        GA1 = addf2(GA1, __shfl_xor_sync(0xffffffffu, GA1, 2, 4));
        GA2 = addf2(GA2, __shfl_xor_sync(0xffffffffu, GA2, 1, 4));
        GA2 = addf2(GA2, __shfl_xor_sync(0xffffffffu, GA2, 2, 4));
        GA3 = addf2(GA3, __shfl_xor_sync(0xffffffffu, GA3, 1, 4));
        GA3 = addf2(GA3, __shfl_xor_sync(0xffffffffu, GA3, 2, 4));
        GB0 = addf2(GB0, __shfl_xor_sync(0xffffffffu, GB0, 1, 4));
        GB0 = addf2(GB0, __shfl_xor_sync(0xffffffffu, GB0, 2, 4));
        GB1 = addf2(GB1, __shfl_xor_sync(0xffffffffu, GB1, 1, 4));
        GB1 = addf2(GB1, __shfl_xor_sync(0xffffffffu, GB1, 2, 4));
        GB2 = addf2(GB2, __shfl_xor_sync(0xffffffffu, GB2, 1, 4));
        GB2 = addf2(GB2, __shfl_xor_sync(0xffffffffu, GB2, 2, 4));
        GB3 = addf2(GB3, __shfl_xor_sync(0xffffffffu, GB3, 1, 4));
        GB3 = addf2(GB3, __shfl_xor_sync(0xffffffffu, GB3, 2, 4));

        ull b20 = uB2[0], b21 = uB2[1], b22 = uB2[2], b23 = uB2[3];
        ull w0 = uWh2[0], w1 = uWh2[1], w2 = uWh2[2], w3 = uWh2[3];
        ull w4 = uWh2[4], w5 = uWh2[5], w6 = uWh2[6], w7 = uWh2[7];

        {   // element A layer-2 cell
            GA0 = addf2(GA0, b20); GA1 = addf2(GA1, b21);
            GA2 = addf2(GA2, b22); GA3 = addf2(GA3, b23);
            ull hx = dup2(h2xA), hy = dup2(h2yA);
            GA0 = ffma2(hx, w0, GA0); GA0 = ffma2(hy, w1, GA0);
            GA1 = ffma2(hx, w2, GA1); GA1 = ffma2(hy, w3, GA1);
            GA2 = ffma2(hx, w4, GA2); GA2 = ffma2(hy, w5, GA2);
            GA3 = ffma2(hx, w6, GA3); GA3 = ffma2(hy, w7, GA3);
            float2 gi=unpack2(GA0), gf=unpack2(GA1), gg=unpack2(GA2), go=unpack2(GA3);
            float i0=sigf(gi.x), i1=sigf(gi.y), f0=sigf(gf.x), f1=sigf(gf.y);
            float t0=tanh_f(gg.x), t1=tanh_f(gg.y), o0=sigf(go.x), o1=sigf(go.y);
            c2xA = fmaf(f0, c2xA, i0 * t0);
            c2yA = fmaf(f1, c2yA, i1 * t1);
            h2xA = o0 * tanh_f(c2xA);
            h2yA = o1 * tanh_f(c2yA);
        }
        {   // element B layer-2 cell
            GB0 = addf2(GB0, b20); GB1 = addf2(GB1, b21);
            GB2 = addf2(GB2, b22); GB3 = addf2(GB3, b23);
            ull hx = dup2(h2xB), hy = dup2(h2yB);
            GB0 = ffma2(hx, w0, GB0); GB0 = ffma2(hy, w1, GB0);
            GB1 = ffma2(hx, w2, GB1); GB1 = ffma2(hy, w3, GB1);
            GB2 = ffma2(hx, w4, GB2); GB2 = ffma2(hy, w5, GB2);
            GB3 = ffma2(hx, w6, GB3); GB3 = ffma2(hy, w7, GB3);
            float2 gi=unpack2(GB0), gf=unpack2(GB1), gg=unpack2(GB2), go=unpack2(GB3);
            float i0=sigf(gi.x), i1=sigf(gi.y), f0=sigf(gf.x), f1=sigf(gf.y);
            float t0=tanh_f(gg.x), t1=tanh_f(gg.y), o0=sigf(go.x), o1=sigf(go.y);
            c2xB = fmaf(f0, c2xB, i0 * t0);
            c2yB = fmaf(f1, c2yB, i1 * t1);
            h2xB = o0 * tanh_f(c2xB);
            h2yB = o1 * tanh_f(c2yB);
        }

        if (lead){
            size_t o = (size_t)t * NB;
            g_scr[o + eA] = h2xA;  g_scr[o + eB] = h2xB;
            g_scr[(size_t)NL*NB + o + eA] = h2yA;  g_scr[(size_t)NL*NB + o + eB] = h2yB;
            g_scr[(size_t)2*NL*NB + o + eA] = fmaf(g_eps[o + eA], __expf(0.5f * h2yA), h2xA);
            g_scr[(size_t)2*NL*NB + o + eB] = fmaf(g_eps[o + eB], __expf(0.5f * h2yB), h2xB);
        }

        if (t < 127){   // rank-1 x-projection update (weights shared A/B)
            ull mA = dup2(__ldg(&g_muT[(size_t)t * NB + eA]));
            ull mB = dup2(__ldg(&g_muT[(size_t)t * NB + eB]));
            const ull* xc = Xu + t * 40;
#pragma unroll
            for (int k = 0; k < 5; ++k){
                ull wi = __ldg(&xc[j0 + k]), wg = __ldg(&xc[20 + j0 + k]);
                aIFA[k] = ffma2(mA, wi, aIFA[k]); aGOA[k] = ffma2(mA, wg, aGOA[k]);
                aIFB[k] = ffma2(mB, wi, aIFB[k]); aGOB[k] = ffma2(mB, wg, aGOB[k]);
            }
            if (t == 1){   // col 0 switches first_input -> mu[:,0] after step 1
                ull pA = dup2(dA), pB = dup2(dB);
#pragma unroll
                for (int k = 0; k < 5; ++k){
                    ull wi = __ldg(&Xu[j0 + k]), wg = __ldg(&Xu[20 + j0 + k]);
                    aIFA[k] = ffma2(pA, wi, aIFA[k]); aGOA[k] = ffma2(pA, wg, aGOA[k]);
                    aIFB[k] = ffma2(pB, wi, aIFB[k]); aGOB[k] = ffma2(pB, wg, aGOB[k]);
                }
            }
        }
    }
}

extern "C" void kernel_launch(void* const* d_in, const int* in_sizes, int n_in,
                              void* d_out, int out_size){
    (void)in_sizes; (void)n_in; (void)out_size;
    dim3 tb(32, 8);
    xpack_kernel<<<20, 256>>>((const float*)d_in[2]);
    mu_transpose_kernel<<<dim3(NL/32, NB/32), tb>>>((const float*)d_in[0]);
    eps_kernel<<<(NL * NB) / 256, 256>>>();
    lstm_kernel<<<NB / 64, 128>>>(
        (const float*)d_in[1],
        (const float*)d_in[3],
        (const float*)d_in[4], (const float*)d_in[5],
        (const float*)d_in[6], (const float*)d_in[7],
        (const float*)d_in[8], (const float*)d_in[9]);
    out_transpose_kernel<<<dim3(NL/32, NB/32, 3), tb>>>((float*)d_out);
}

// round 17
// speedup vs baseline: 1.4296x; 1.0725x over previous
#include <cuda_runtime.h>
#include <cstdint>

typedef unsigned long long ull;
#define NB 32768
#define NL 128

__device__ float  g_eps[NL * NB];       // eps[t][b]
__device__ float  g_muT[NL * NB];       // mu transposed: [t][b]
__device__ float  g_scr[3 * NL * NB];   // outputs transposed: [k][t][b]
__device__ float2 g_Xpack[127 * 40];    // W_ih1 col c: [c*40+j]=(Wi,Wf), [c*40+20+j]=(Wg,Wo)

__device__ __forceinline__ ull ffma2(ull a, ull b, ull c){
    ull d; asm("fma.rn.f32x2 %0, %1, %2, %3;" : "=l"(d) : "l"(a), "l"(b), "l"(c)); return d;
}
__device__ __forceinline__ ull addf2(ull a, ull b){
    ull d; asm("add.rn.f32x2 %0, %1, %2;" : "=l"(d) : "l"(a), "l"(b)); return d;
}
__device__ __forceinline__ ull dup2(float f){
    ull r; asm("mov.b64 %0, {%1, %1};" : "=l"(r) : "f"(f)); return r;
}
__device__ __forceinline__ float2 unpack2(ull v){
    float2 r; asm("mov.b64 {%0, %1}, %2;" : "=f"(r.x), "=f"(r.y) : "l"(v)); return r;
}
// hardware tanh (MUFU.TANH, sm_75+): 1 op, lat~16, abs err ~5e-4
__device__ __forceinline__ float tanhap(float x){
    float y; asm("tanh.approx.f32 %0, %1;" : "=f"(y) : "f"(x)); return y;
}
__device__ __forceinline__ float sigf(float x){ return fmaf(0.5f, tanhap(0.5f * x), 0.5f); }
__device__ __forceinline__ float tanh_f(float x){ return tanhap(x); }

// JAX threefry2x32, key=(0,42), partitionable (validated R11). KEEP EXACT.
#define TFR(r) { x0 += x1; x1 = __funnelshift_l(x1, x1, (r)); x1 ^= x0; }
__device__ __forceinline__ uint32_t tf_bits(uint32_t i){
    const uint32_t K0 = 0u, K1 = 42u, K2 = 0x1BD11BDAu ^ 42u;
    uint32_t x0 = K0, x1 = i + K1;
    TFR(13) TFR(15) TFR(26) TFR(6)  x0 += K1; x1 += K2 + 1u;
    TFR(17) TFR(29) TFR(16) TFR(24) x0 += K2; x1 += K0 + 2u;
    TFR(13) TFR(15) TFR(26) TFR(6)  x0 += K0; x1 += K1 + 3u;
    TFR(17) TFR(29) TFR(16) TFR(24) x0 += K1; x1 += K2 + 4u;
    TFR(13) TFR(15) TFR(26) TFR(6)  x0 += K2; x1 += K0 + 5u;
    return x0 ^ x1;
}
__device__ __forceinline__ float erfinv_f(float x){
    float w = -__logf(fmaf(x, -x, 1.0f)), p;
    if (w < 5.0f){
        w -= 2.5f;
        p = 2.81022636e-08f;
        p = fmaf(p, w, 3.43273939e-07f);  p = fmaf(p, w, -3.5233877e-06f);
        p = fmaf(p, w, -4.39150654e-06f); p = fmaf(p, w, 0.00021858087f);
        p = fmaf(p, w, -0.00125372503f);  p = fmaf(p, w, -0.00417768164f);
        p = fmaf(p, w, 0.246640727f);     p = fmaf(p, w, 1.50140941f);
    } else {
        w = __fsqrt_rn(w) - 3.0f;
        p = -0.000200214257f;
        p = fmaf(p, w, 0.000100950558f);  p = fmaf(p, w, 0.00134934322f);
        p = fmaf(p, w, -0.00367342844f);  p = fmaf(p, w, 0.00573950773f);
        p = fmaf(p, w, -0.0076224613f);   p = fmaf(p, w, 0.00943887047f);
        p = fmaf(p, w, 1.00167406f);      p = fmaf(p, w, 2.83297682f);
    }
    return p * x;
}
__global__ void eps_kernel(){
    uint32_t i = blockIdx.x * 256u + threadIdx.x;
    uint32_t bits = tf_bits(i);
    float u01 = __uint_as_float((bits >> 9) | 0x3f800000u) - 1.0f;
    const float mn = __uint_as_float(0xBF7FFFFFu);
    float u = fmaxf(mn, fmaf(u01, 2.0f, mn));
    g_eps[i] = __uint_as_float(0x3FB504F3u) * erfinv_f(u);
}

__global__ void xpack_kernel(const float* __restrict__ Wih1){
    int idx = blockIdx.x * 256 + threadIdx.x;
    if (idx >= 127*40) return;
    int c = idx / 40, q = idx - c*40;
    int j  = (q < 20) ? q : (q - 20);
    int r0 = (q < 20) ? j : (40 + j);
    int r1 = (q < 20) ? (20 + j) : (60 + j);
    g_Xpack[idx] = make_float2(Wih1[r0*127 + c], Wih1[r1*127 + c]);
}

__global__ void mu_transpose_kernel(const float* __restrict__ mu){
    __shared__ float tile[32][33];
    int t0 = blockIdx.x * 32, b0 = blockIdx.y * 32;
    int tx = threadIdx.x, ty = threadIdx.y;           // block (32,8)
#pragma unroll
    for (int r = 0; r < 32; r += 8)
        tile[ty + r][tx] = mu[(size_t)(b0 + ty + r) * NL + t0 + tx];
    __syncthreads();
#pragma unroll
    for (int r = 0; r < 32; r += 8)
        g_muT[(size_t)(t0 + ty + r) * NB + b0 + tx] = tile[tx][ty + r];
}

__global__ void out_transpose_kernel(float* __restrict__ out){
    __shared__ float tile[32][33];
    const float* src = g_scr + (size_t)blockIdx.z * NL * NB;
    float* dst = out + (size_t)blockIdx.z * NL * NB;
    int t0 = blockIdx.x * 32, b0 = blockIdx.y * 32;
    int tx = threadIdx.x, ty = threadIdx.y;
#pragma unroll
    for (int r = 0; r < 32; r += 8)
        tile[ty + r][tx] = src[(size_t)(t0 + ty + r) * NB + b0 + tx];
    __syncthreads();
#pragma unroll
    for (int r = 0; r < 32; r += 8)
        dst[(size_t)(b0 + ty + r) * NL + t0 + tx] = tile[tx][ty + r];
}

#define WH_STRIDE 42   // padded: quad addresses land on disjoint banks

struct __align__(16) Smem {
    float2 WH[20*WH_STRIDE]; // [j*42 + g*10 + q] = (Whh1[g*20+j][2q], ..[2q+1])
    float2 W2[160];          // [p*40+d] = (Wih2[2p][d], Wih2[2p+1][d]); d<20:h, d>=20:c
    float2 Wh2[8];
    float2 B2[4];
    float2 BIF[20];
    float2 BGO[20];
    float  hbuf[64*20];      // per-element h vectors (quad-shared)
};

__global__ void __launch_bounds__(128, 3) lstm_kernel(
    const float* __restrict__ log_var,
    const float* __restrict__ Whh1,
    const float* __restrict__ bih1, const float* __restrict__ bhh1,
    const float* __restrict__ Wih2, const float* __restrict__ Whh2,
    const float* __restrict__ bih2, const float* __restrict__ bhh2)
{
    __shared__ Smem sm;
    const int tid = threadIdx.x;

    for (int idx = tid; idx < 800; idx += 128){
        int j = idx / 40, r = idx - j*40;
        int gg = r / 10, q = r - gg*10;
        int row = gg*20 + j;
        sm.WH[j*WH_STRIDE + r] = make_float2(Whh1[row*20 + 2*q], Whh1[row*20 + 2*q + 1]);
    }
    for (int idx = tid; idx < 160; idx += 128){
        int p = idx / 40, d = idx - p*40;
        sm.W2[idx] = make_float2(Wih2[(2*p)*40 + d], Wih2[(2*p+1)*40 + d]);
    }
    if (tid < 8){
        int p = tid >> 1, e = tid & 1;
        sm.Wh2[tid] = make_float2(Whh2[(2*p)*2 + e], Whh2[(2*p+1)*2 + e]);
    }
    if (tid < 4)
        sm.B2[tid] = make_float2(bih2[2*tid] + bhh2[2*tid], bih2[2*tid+1] + bhh2[2*tid+1]);
    if (tid < 20){
        sm.BIF[tid] = make_float2(bih1[tid]    + bhh1[tid],    bih1[20+tid] + bhh1[20+tid]);
        sm.BGO[tid] = make_float2(bih1[40+tid] + bhh1[40+tid], bih1[60+tid] + bhh1[60+tid]);
    }
    __syncthreads();

    const int g    = tid & 3;
    const int j0   = g * 5;
    const int quad = (tid & 31) >> 2;
    const int wrp  = tid >> 5;
    const int eb   = blockIdx.x * 64 + wrp * 16;
    const int eA   = eb + quad;
    const int eB   = eb + 8 + quad;
    const bool lead = (g == 0);

    float* hrowA = sm.hbuf + (wrp*16 + quad) * 20;
    float* hrowB = sm.hbuf + (wrp*16 + 8 + quad) * 20;

    const ull* uBIF = reinterpret_cast<const ull*>(sm.BIF);
    const ull* uBGO = reinterpret_cast<const ull*>(sm.BGO);
    const ull* Xu   = reinterpret_cast<const ull*>(g_Xpack);
    const ull* uW2  = reinterpret_cast<const ull*>(sm.W2);
    const ull* uWh2 = reinterpret_cast<const ull*>(sm.Wh2);
    const ull* uB2  = reinterpret_cast<const ull*>(sm.B2);

    ull aIFA[5], aGOA[5], aIFB[5], aGOB[5];
    float c1A[5], c1B[5];
#pragma unroll
    for (int k = 0; k < 5; ++k){
        aIFA[k] = uBIF[j0+k]; aGOA[k] = uBGO[j0+k];
        aIFB[k] = aIFA[k];    aGOB[k] = aGOA[k];
        c1A[k] = 0.0f; c1B[k] = 0.0f;
        hrowA[j0+k] = 0.0f; hrowB[j0+k] = 0.0f;
    }
    float h2xA=0.f,h2yA=0.f,c2xA=0.f,c2yA=0.f;
    float h2xB=0.f,h2yB=0.f,c2xB=0.f,c2yB=0.f;
    __syncwarp();

    const float mu0A = __ldg(&g_muT[eA]),  mu0B = __ldg(&g_muT[eB]);
    const float firstA = fmaf(g_eps[eA], __expf(0.5f * __ldg(&log_var[(size_t)eA * NL])), mu0A);
    const float firstB = fmaf(g_eps[eB], __expf(0.5f * __ldg(&log_var[(size_t)eB * NL])), mu0B);
    const float dA = mu0A - firstA, dB = mu0B - firstB;
    if (lead){
        g_scr[eA] = 0.0f; g_scr[(size_t)NL*NB + eA] = 1.0f; g_scr[(size_t)2*NL*NB + eA] = firstA;
        g_scr[eB] = 0.0f; g_scr[(size_t)NL*NB + eB] = 1.0f; g_scr[(size_t)2*NL*NB + eB] = firstB;
    }

    {   // step-1 x-proj: col 0 * first_input
        ull fA = dup2(firstA), fB = dup2(firstB);
#pragma unroll
        for (int k = 0; k < 5; ++k){
            ull wi = __ldg(&Xu[j0 + k]), wg = __ldg(&Xu[20 + j0 + k]);
            aIFA[k] = ffma2(fA, wi, aIFA[k]); aGOA[k] = ffma2(fA, wg, aGOA[k]);
            aIFB[k] = ffma2(fB, wi, aIFB[k]); aGOB[k] = ffma2(fB, wg, aGOB[k]);
        }
    }

#pragma unroll 1
    for (int t = 1; t < NL; ++t){
        // ---- load previous h for both elements (quad-shared smem) ----
        ull hEA[10], hEB[10];
        {
            const ull* ha = reinterpret_cast<const ull*>(hrowA);
            const ull* hb = reinterpret_cast<const ull*>(hrowB);
#pragma unroll
            for (int q = 0; q < 10; ++q){ hEA[q] = ha[q]; hEB[q] = hb[q]; }
        }
        __syncwarp();   // all quad lanes' reads precede any lane's stores below

        ull GA0=0,GA1=0,GA2=0,GA3=0, GB0=0,GB1=0,GB2=0,GB3=0;

#pragma unroll
        for (int k = 0; k < 5; ++k){
            const int j = j0 + k;
            const ulonglong2* wU = reinterpret_cast<const ulonglong2*>(sm.WH + j*WH_STRIDE);
            ull aiA=0,afA=0,agA=0,aoA=0, aiB=0,afB=0,agB=0,aoB=0;
#pragma unroll
            for (int q = 0; q < 5; ++q){
                ulonglong2 wi = wU[q], wf = wU[5+q], wg = wU[10+q], wo = wU[15+q];
                ull a0 = hEA[2*q], a1 = hEA[2*q+1];
                ull b0 = hEB[2*q], b1 = hEB[2*q+1];
                aiA = ffma2(a0, wi.x, aiA); aiA = ffma2(a1, wi.y, aiA);
                afA = ffma2(a0, wf.x, afA); afA = ffma2(a1, wf.y, afA);
                agA = ffma2(a0, wg.x, agA); agA = ffma2(a1, wg.y, agA);
                aoA = ffma2(a0, wo.x, aoA); aoA = ffma2(a1, wo.y, aoA);
                aiB = ffma2(b0, wi.x, aiB); aiB = ffma2(b1, wi.y, aiB);
                afB = ffma2(b0, wf.x, afB); afB = ffma2(b1, wf.y, afB);
                agB = ffma2(b0, wg.x, agB); agB = ffma2(b1, wg.y, agB);
                aoB = ffma2(b0, wo.x, aoB); aoB = ffma2(b1, wo.y, aoB);
            }
            // shared layer-2 weight loads
            ull w2h0 = uW2[j],    w2h1 = uW2[40+j],  w2h2 = uW2[80+j],  w2h3 = uW2[120+j];
            ull w2c0 = uW2[20+j], w2c1 = uW2[60+j],  w2c2 = uW2[100+j], w2c3 = uW2[140+j];
            {   // element A cell
                float2 vi=unpack2(aiA), vf=unpack2(afA), vg=unpack2(agA), vo=unpack2(aoA);
                float2 xif=unpack2(aIFA[k]), xgo=unpack2(aGOA[k]);
                float ig = sigf(vi.x + vi.y + xif.x);
                float fg = sigf(vf.x + vf.y + xif.y);
                float gg = tanh_f(vg.x + vg.y + xgo.x);
                float og = sigf(vo.x + vo.y + xgo.y);
                float cn = fmaf(fg, c1A[k], ig * gg);
                c1A[k] = cn;
                float hj = og * tanh_f(cn);
                hrowA[j] = hj;
                ull lh = dup2(fmaxf(hj, 0.01f * hj));
                GA0 = ffma2(lh, w2h0, GA0); GA1 = ffma2(lh, w2h1, GA1);
                GA2 = ffma2(lh, w2h2, GA2); GA3 = ffma2(lh, w2h3, GA3);
                ull lc = dup2(fmaxf(cn, 0.01f * cn));
                GA0 = ffma2(lc, w2c0, GA0); GA1 = ffma2(lc, w2c1, GA1);
                GA2 = ffma2(lc, w2c2, GA2); GA3 = ffma2(lc, w2c3, GA3);
            }
            {   // element B cell
                float2 vi=unpack2(aiB), vf=unpack2(afB), vg=unpack2(agB), vo=unpack2(aoB);
                float2 xif=unpack2(aIFB[k]), xgo=unpack2(aGOB[k]);
                float ig = sigf(vi.x + vi.y + xif.x);
                float fg = sigf(vf.x + vf.y + xif.y);
                float gg = tanh_f(vg.x + vg.y + xgo.x);
                float og = sigf(vo.x + vo.y + xgo.y);
                float cn = fmaf(fg, c1B[k], ig * gg);
                c1B[k] = cn;
                float hj = og * tanh_f(cn);
                hrowB[j] = hj;
                ull lh = dup2(fmaxf(hj, 0.01f * hj));
                GB0 = ffma2(lh, w2h0, GB0); GB1 = ffma2(lh, w2h1, GB1);
                GB2 = ffma2(lh, w2h2, GB2); GB3 = ffma2(lh, w2h3, GB3);
                ull lc = dup2(fmaxf(cn, 0.01f * cn));
                GB0 = ffma2(lc, w2c0, GB0); GB1 = ffma2(lc, w2c1, GB1);
                GB2 = ffma2(lc, w2c2, GB2); GB3 = ffma2(lc, w2c3, GB3);
            }
        }
        __syncwarp();   // stores complete before next step's loads

        // ---- quad reductions ----
        GA0 = addf2(GA0, __shfl_xor_sync(0xffffffffu, GA0, 1, 4));
        GA0 = addf2(GA0, __shfl_xor_sync(0xffffffffu, GA0, 2, 4));
        GA1 = addf2(GA1, __shfl_xor_sync(0xffffffffu, GA1, 1, 4));
        GA1 = addf2(GA1, __shfl_xor_sync(0xffffffffu, GA1, 2, 4));
        GA2 = addf2(GA2, __shfl_xor_sync(0xffffffffu, GA2, 1, 4));
        GA2 = addf2(GA2, __shfl_xor_sync(0xffffffffu, GA2, 2, 4));
        GA3 = addf2(GA3, __shfl_xor_sync(0xffffffffu, GA3, 1, 4));
        GA3 = addf2(GA3, __shfl_xor_sync(0xffffffffu, GA3, 2, 4));
        GB0 = addf2(GB0, __shfl_xor_sync(0xffffffffu, GB0, 1, 4));
        GB0 = addf2(GB0, __shfl_xor_sync(0xffffffffu, GB0, 2, 4));
        GB1 = addf2(GB1, __shfl_xor_sync(0xffffffffu, GB1, 1, 4));
        GB1 = addf2(GB1, __shfl_xor_sync(0xffffffffu, GB1, 2, 4));
        GB2 = addf2(GB2, __shfl_xor_sync(0xffffffffu, GB2, 1, 4));
        GB2 = addf2(GB2, __shfl_xor_sync(0xffffffffu, GB2, 2, 4));
        GB3 = addf2(GB3, __shfl_xor_sync(0xffffffffu, GB3, 1, 4));
        GB3 = addf2(GB3, __shfl_xor_sync(0xffffffffu, GB3, 2, 4));

        ull b20 = uB2[0], b21 = uB2[1], b22 = uB2[2], b23 = uB2[3];
        ull w0 = uWh2[0], w1 = uWh2[1], w2 = uWh2[2], w3 = uWh2[3];
        ull w4 = uWh2[4], w5 = uWh2[5], w6 = uWh2[6], w7 = uWh2[7];

        {   // element A layer-2 cell
            GA0 = addf2(GA0, b20); GA1 = addf2(GA1, b21);
            GA2 = addf2(GA2, b22); GA3 = addf2(GA3, b23);
            ull hx = dup2(h2xA), hy = dup2(h2yA);
            GA0 = ffma2(hx, w0, GA0); GA0 = ffma2(hy, w1, GA0);
            GA1 = ffma2(hx, w2, GA1); GA1 = ffma2(hy, w3, GA1);
            GA2 = ffma2(hx, w4, GA2); GA2 = ffma2(hy, w5, GA2);
            GA3 = ffma2(hx, w6, GA3); GA3 = ffma2(hy, w7, GA3);
            float2 gi=unpack2(GA0), gf=unpack2(GA1), gg=unpack2(GA2), go=unpack2(GA3);
            float i0=sigf(gi.x), i1=sigf(gi.y), f0=sigf(gf.x), f1=sigf(gf.y);
            float t0=tanh_f(gg.x), t1=tanh_f(gg.y), o0=sigf(go.x), o1=sigf(go.y);
            c2xA = fmaf(f0, c2xA, i0 * t0);
            c2yA = fmaf(f1, c2yA, i1 * t1);
            h2xA = o0 * tanh_f(c2xA);
            h2yA = o1 * tanh_f(c2yA);
        }
        {   // element B layer-2 cell
            GB0 = addf2(GB0, b20); GB1 = addf2(GB1, b21);
            GB2 = addf2(GB2, b22); GB3 = addf2(GB3, b23);
            ull hx = dup2(h2xB), hy = dup2(h2yB);
            GB0 = ffma2(hx, w0, GB0); GB0 = ffma2(hy, w1, GB0);
            GB1 = ffma2(hx, w2, GB1); GB1 = ffma2(hy, w3, GB1);
            GB2 = ffma2(hx, w4, GB2); GB2 = ffma2(hy, w5, GB2);
            GB3 = ffma2(hx, w6, GB3); GB3 = ffma2(hy, w7, GB3);
            float2 gi=unpack2(GB0), gf=unpack2(GB1), gg=unpack2(GB2), go=unpack2(GB3);
            float i0=sigf(gi.x), i1=sigf(gi.y), f0=sigf(gf.x), f1=sigf(gf.y);
            float t0=tanh_f(gg.x), t1=tanh_f(gg.y), o0=sigf(go.x), o1=sigf(go.y);
            c2xB = fmaf(f0, c2xB, i0 * t0);
            c2yB = fmaf(f1, c2yB, i1 * t1);
            h2xB = o0 * tanh_f(c2xB);
            h2yB = o1 * tanh_f(c2yB);
        }

        if (lead){
            size_t o = (size_t)t * NB;
            g_scr[o + eA] = h2xA;  g_scr[o + eB] = h2xB;
            g_scr[(size_t)NL*NB + o + eA] = h2yA;  g_scr[(size_t)NL*NB + o + eB] = h2yB;
            g_scr[(size_t)2*NL*NB + o + eA] = fmaf(g_eps[o + eA], __expf(0.5f * h2yA), h2xA);
            g_scr[(size_t)2*NL*NB + o + eB] = fmaf(g_eps[o + eB], __expf(0.5f * h2yB), h2xB);
        }

        if (t < 127){   // rank-1 x-projection update (weights shared A/B)
            ull mA = dup2(__ldg(&g_muT[(size_t)t * NB + eA]));
            ull mB = dup2(__ldg(&g_muT[(size_t)t * NB + eB]));
            const ull* xc = Xu + t * 40;
#pragma unroll
            for (int k = 0; k < 5; ++k){
                ull wi = __ldg(&xc[j0 + k]), wg = __ldg(&xc[20 + j0 + k]);
                aIFA[k] = ffma2(mA, wi, aIFA[k]); aGOA[k] = ffma2(mA, wg, aGOA[k]);
                aIFB[k] = ffma2(mB, wi, aIFB[k]); aGOB[k] = ffma2(mB, wg, aGOB[k]);
            }
            if (t == 1){   // col 0 switches first_input -> mu[:,0] after step 1
                ull pA = dup2(dA), pB = dup2(dB);
#pragma unroll
                for (int k = 0; k < 5; ++k){
                    ull wi = __ldg(&Xu[j0 + k]), wg = __ldg(&Xu[20 + j0 + k]);
                    aIFA[k] = ffma2(pA, wi, aIFA[k]); aGOA[k] = ffma2(pA, wg, aGOA[k]);
                    aIFB[k] = ffma2(pB, wi, aIFB[k]); aGOB[k] = ffma2(pB, wg, aGOB[k]);
                }
            }
        }
    }
}

extern "C" void kernel_launch(void* const* d_in, const int* in_sizes, int n_in,
                              void* d_out, int out_size){
    (void)in_sizes; (void)n_in; (void)out_size;
    dim3 tb(32, 8);
    xpack_kernel<<<20, 256>>>((const float*)d_in[2]);
    mu_transpose_kernel<<<dim3(NL/32, NB/32), tb>>>((const float*)d_in[0]);
    eps_kernel<<<(NL * NB) / 256, 256>>>();
    lstm_kernel<<<NB / 64, 128>>>(
        (const float*)d_in[1],
        (const float*)d_in[3],
        (const float*)d_in[4], (const float*)d_in[5],
        (const float*)d_in[6], (const float*)d_in[7],
        (const float*)d_in[8], (const float*)d_in[9]);
    out_transpose_kernel<<<dim3(NL/32, NB/32, 3), tb>>>((float*)d_out);
}